// round 8
// baseline (speedup 1.0000x reference)
#include <cuda_runtime.h>
#include <cuda_fp16.h>

#define ALPHA 0.2f
#define BN_EPS 1e-5f
#define THREADS 640
#define WARPS 20

typedef unsigned int u32;
typedef unsigned long long u64;

__device__ __forceinline__ u32 pkh(float a, float b){
    __half2 h = __floats2half2_rn(a, b);
    return *(u32*)&h;
}
__device__ __forceinline__ u64 ffma2(u64 a, u64 b, u64 c){
    u64 d; asm("fma.rn.f32x2 %0, %1, %2, %3;" : "=l"(d) : "l"(a), "l"(b), "l"(c)); return d;
}
__device__ __forceinline__ u64 pk(float lo, float hi){
    u64 r; asm("mov.b64 %0, {%1, %2};" : "=l"(r) : "f"(lo), "f"(hi)); return r;
}
__device__ __forceinline__ float hsum(u64 v){
    float x, y; asm("mov.b64 {%0, %1}, %2;" : "=f"(x), "=f"(y) : "l"(v)); return x + y;
}
__device__ __forceinline__ float wsum(float v){
    #pragma unroll
    for (int d = 16; d > 0; d >>= 1) v += __shfl_xor_sync(0xffffffffu, v, d);
    return v;
}
// m16n8k16 fp16 MMA, fp32 accum
__device__ __forceinline__ void mma16(float4& d, u32 a0, u32 a1, u32 a2, u32 a3, u32 b0, u32 b1){
    asm("mma.sync.aligned.m16n8k16.row.col.f32.f16.f16.f32 "
        "{%0,%1,%2,%3}, {%4,%5,%6,%7}, {%8,%9}, {%0,%1,%2,%3};"
        : "+f"(d.x), "+f"(d.y), "+f"(d.z), "+f"(d.w)
        : "r"(a0), "r"(a1), "r"(a2), "r"(a3), "r"(b0), "r"(b1));
}

// ---- shared memory layout (32-bit slots) ----
#define BF1_OFF   0        // [8 q][9 t][32 lane] uint2 fp16 B frags L1 (t=8: score cols) = 4608
#define BF2_OFF   4608     // [4 q][5 t][32] uint2 (t=4: score cols) = 1280 -> 5888
#define WL2_OFF   5888     // [13 k][5 n][32 lane] float2 = 4160 -> 10048
#define SC1_OFF   10048
#define SH1_OFF   10056
#define SC2_OFF   10064
#define SH2_OFF   10072
#define BL_OFF    10080    // 13 (pad 16) -> 10096
#define SCR_OFF   10096
// per-warp scratch (1568 slots):
//   phase 1: xh[2][10 rows][68 u32] fp16x2 x rows = 1360
//   overlays in [0,1360): H f32 (stride 68, 680/batch) -> h2 fp16x2 (stride 36)
//                         -> hh f32 (stride 34)
//   SB1 [1360,1400)  SB2 [1400,1440)  AB [1440,1568): attn 2 x 64
// init-time temp (block scope, overlays warp scratch): w1a[0,125), w2a[128,253),
//   w1a2[256,320), w2a2[320,384)
#define WSCR      1568
#define SMEM_FLOATS (SCR_OFF + WARPS*WSCR)   // 41456 slots = 165824 bytes

__global__ void __launch_bounds__(THREADS, 1) gat_fused_kernel(
    const float* __restrict__ x,
    const float* __restrict__ Wt1, const float* __restrict__ a11, const float* __restrict__ a21,
    const float* __restrict__ g1,  const float* __restrict__ b1,  const float* __restrict__ m1, const float* __restrict__ v1,
    const float* __restrict__ Wt2, const float* __restrict__ a12, const float* __restrict__ a22,
    const float* __restrict__ g2,  const float* __restrict__ b2,  const float* __restrict__ m2, const float* __restrict__ v2,
    const float* __restrict__ Wl,  const float* __restrict__ bl,
    float* __restrict__ out, int B)
{
    extern __shared__ float sm[];
    const int tid = threadIdx.x;

    // -------- init phase A: folded score vectors w = W^T a (fp32, to temp smem) ----
    {
        float* wtmp = sm + SCR_OFF;
        for (int i = tid; i < 250; i += THREADS){
            int v = (i >= 125), k = i - v*125;
            const float* av = v ? a21 : a11;
            float s = 0.f;
            #pragma unroll 8
            for (int n = 0; n < 64; n++) s += av[n] * Wt1[n*125 + k];
            wtmp[v*128 + k] = s;
        }
        for (int i = tid; i < 128; i += THREADS){
            int v = (i >= 64), k = i & 63;
            const float* av = v ? a22 : a12;
            float s = 0.f;
            #pragma unroll 8
            for (int n = 0; n < 32; n++) s += av[n] * Wt2[n*64 + k];
            wtmp[256 + v*64 + k] = s;
        }
    }
    __syncthreads();

    // -------- init phase B: stage fp16 B-fragments (incl. score tiles) -------------
    {
        const float* w1a  = sm + SCR_OFF;
        const float* w2a  = sm + SCR_OFF + 128;
        const float* w1a2 = sm + SCR_OFF + 256;
        const float* w2a2 = sm + SCR_OFF + 320;

        uint2* bf1 = (uint2*)(sm + BF1_OFF);
        for (int i = tid; i < 8*9*32; i += THREADS){
            int l = i & 31, tt = i >> 5;
            int t = tt % 9, q = tt / 9;
            int k0 = 16*q + 2*(l & 3);
            uint2 val;
            if (t < 8){
                int n = 8*t + (l >> 2);
                float w0 = (k0   < 125) ? Wt1[n*125 + k0    ] : 0.f;
                float w1 = (k0+1 < 125) ? Wt1[n*125 + k0 + 1] : 0.f;
                float w8 = (k0+8 < 125) ? Wt1[n*125 + k0 + 8] : 0.f;
                float w9 = (k0+9 < 125) ? Wt1[n*125 + k0 + 9] : 0.f;
                val = make_uint2(pkh(w0, w1), pkh(w8, w9));
            } else {
                int c = l >> 2;   // col 64+c: c==0 -> w1a, c==1 -> w2a, else 0
                const float* wv = (c == 0) ? w1a : w2a;
                if (c < 2){
                    float w0 = (k0   < 125) ? wv[k0    ] : 0.f;
                    float w1 = (k0+1 < 125) ? wv[k0 + 1] : 0.f;
                    float w8 = (k0+8 < 125) ? wv[k0 + 8] : 0.f;
                    float w9 = (k0+9 < 125) ? wv[k0 + 9] : 0.f;
                    val = make_uint2(pkh(w0, w1), pkh(w8, w9));
                } else val = make_uint2(0u, 0u);
            }
            bf1[(q*9 + t)*32 + l] = val;
        }
        uint2* bf2 = (uint2*)(sm + BF2_OFF);
        for (int i = tid; i < 4*5*32; i += THREADS){
            int l = i & 31, tt = i >> 5;
            int t = tt % 5, q = tt / 5;
            int k0 = 16*q + 2*(l & 3);
            uint2 val;
            if (t < 4){
                int n = 8*t + (l >> 2);
                val = make_uint2(pkh(Wt2[n*64 + k0    ], Wt2[n*64 + k0 + 1]),
                                 pkh(Wt2[n*64 + k0 + 8], Wt2[n*64 + k0 + 9]));
            } else {
                int c = l >> 2;
                const float* wv = (c == 0) ? w1a2 : w2a2;
                if (c < 2)
                    val = make_uint2(pkh(wv[k0], wv[k0+1]), pkh(wv[k0+8], wv[k0+9]));
                else val = make_uint2(0u, 0u);
            }
            bf2[(q*5 + t)*32 + l] = val;
        }
        float2* wlp = (float2*)(sm + WL2_OFF);       // [k][n][lane]
        for (int i = tid; i < 13*5*32; i += THREADS){
            int k = i / 160, r = i - k*160;
            int n = r >> 5, l = r & 31;
            wlp[i] = make_float2(Wl[k*320 + n*64 + l], Wl[k*320 + n*64 + 32 + l]);
        }
        if (tid < 5){
            float sc = g1[tid] * rsqrtf(v1[tid] + BN_EPS);
            sm[SC1_OFF+tid] = sc; sm[SH1_OFF+tid] = b1[tid] - m1[tid]*sc;
            float s2c = g2[tid] * rsqrtf(v2[tid] + BN_EPS);
            sm[SC2_OFF+tid] = s2c; sm[SH2_OFF+tid] = b2[tid] - m2[tid]*s2c;
        }
        if (tid < 13) sm[BL_OFF+tid] = bl[tid];
    }
    __syncthreads();

    const int wid  = tid >> 5, lane = tid & 31;
    const int gid  = lane >> 2, tig = lane & 3;   // fragment coords
    const int hi_ok = (gid < 2);
    const int b0i = (blockIdx.x * WARPS + wid) * 2;
    if (b0i >= B) return;
    const int has_b1 = (b0i + 1 < B);
    const int b1i = has_b1 ? (b0i + 1) : b0i;

    float* ws = sm + SCR_OFF + wid*WSCR;
    u32*   xh = (u32*)ws;                    // fp16x2 x rows, stride 68 u32

    // ---------------- load x (2 batches) -> fp16 A rows ----------------
    {
        const int L2 = 2*lane;
        #pragma unroll
        for (int bi = 0; bi < 2; bi++){
            const float* xg = x + (size_t)(bi ? b1i : b0i) * 1250;
            u32* xsb = xh + bi*680;
            #pragma unroll
            for (int inp = 0; inp < 2; inp++)
                #pragma unroll
                for (int n = 0; n < 5; n++){
                    const float* src = xg + n*250 + inp*125;
                    u32* dst = xsb + (inp*5 + n)*68;
                    dst[lane] = pkh(src[L2], src[L2+1]);
                    float c0 = (L2+64 < 125) ? src[L2+64] : 0.f;
                    float c1 = (L2+65 < 125) ? src[L2+65] : 0.f;
                    dst[lane+32] = pkh(c0, c1);
                }
        }
    }
    __syncwarp();

    // ------- layer 1 MMA: 9 N-tiles (8 data + 1 score), K=128 in 8 k16-steps -----
    float4 d1[2][9];
    #pragma unroll
    for (int bi = 0; bi < 2; bi++)
        #pragma unroll
        for (int t = 0; t < 9; t++) d1[bi][t] = make_float4(0.f, 0.f, 0.f, 0.f);
    {
        const int hi_row = hi_ok ? (gid+8)*68 : 0;
        const u32* xa0lo = xh + gid*68 + tig;
        const u32* xa0hi = xh + hi_row + tig;
        const u32* xa1lo = xa0lo + 680;
        const u32* xa1hi = xa0hi + 680;
        const uint2* bf1 = (const uint2*)(sm + BF1_OFF);
        #pragma unroll
        for (int q = 0; q < 8; q++){
            u32 a00 = xa0lo[8*q], a01 = xa0hi[8*q];
            u32 a02 = xa0lo[8*q + 4], a03 = xa0hi[8*q + 4];
            u32 a10 = xa1lo[8*q], a11r = xa1hi[8*q];
            u32 a12r = xa1lo[8*q + 4], a13 = xa1hi[8*q + 4];
            #pragma unroll
            for (int t = 0; t < 9; t++){
                uint2 bb = bf1[(q*9 + t)*32 + lane];
                mma16(d1[0][t], a00, a01, a02, a03, bb.x, bb.y);
                mma16(d1[1][t], a10, a11r, a12r, a13, bb.x, bb.y);
            }
        }
    }
    __syncwarp();   // all xh reads done before H overlay writes

    // ---- layer 1: scores direct from tile 8; spill H rows (f32, stride 68) ------
    #pragma unroll
    for (int bi = 0; bi < 2; bi++){
        float2* sb = (float2*)(ws + 1360) + bi*10;
        if (tig == 0){
            sb[gid] = make_float2(d1[bi][8].x, d1[bi][8].y);
            if (hi_ok) sb[8 + gid] = make_float2(d1[bi][8].z, d1[bi][8].w);
        }
        float* hb = ws + bi*680;   // f32, stride 68
        #pragma unroll
        for (int t = 0; t < 8; t++){
            int col = 8*t + 2*tig;
            *(float2*)(hb + gid*68 + col) = make_float2(d1[bi][t].x, d1[bi][t].y);
            if (hi_ok)
                *(float2*)(hb + (gid+8)*68 + col) = make_float2(d1[bi][t].z, d1[bi][t].w);
        }
    }
    __syncwarp();

    // ---------------- merged layer 1 softmax (20 lanes, both batches) -----------
    {
        int bb_ = lane / 10, r = lane - 10*bb_;
        int g = r / 5, j = r - 5*g;
        if (lane < 20){
            const float2* sb = (const float2*)(ws + 1360) + bb_*10;
            float* abuf = ws + 1440 + bb_*64;
            float t2j = sb[g*5 + j].y;
            float ex[5], cs = 0.f;
            #pragma unroll
            for (int i = 0; i < 5; i++){
                float e = sb[g*5 + i].x + t2j;
                e = (e > 0.f) ? e : ALPHA*e;
                ex[i] = __expf(e);
                cs += ex[i];
            }
            float rc = __fdividef(1.f, cs);
            #pragma unroll
            for (int i = 0; i < 5; i++) abuf[g*32 + i*5 + j] = ex[i]*rc;
        }
    }
    __syncwarp();

    // ---------------- apply1 + BN1 + ReLU -> h2 fp16 (stride 36) ----------------
    #pragma unroll
    for (int bi = 0; bi < 2; bi++){
        const float* hb = ws + bi*680;
        const float* abuf = ws + 1440 + bi*64;
        float Ox[2][5], Oy[2][5];
        #pragma unroll
        for (int inp = 0; inp < 2; inp++)
            #pragma unroll
            for (int i = 0; i < 5; i++){ Ox[inp][i] = 0.f; Oy[inp][i] = 0.f; }
        #pragma unroll
        for (int inp = 0; inp < 2; inp++)
            #pragma unroll
            for (int j = 0; j < 5; j++){
                float2 Hp = *(const float2*)(hb + (inp*5 + j)*68 + 2*lane);
                #pragma unroll
                for (int i = 0; i < 5; i++){
                    float a = abuf[inp*32 + i*5 + j];
                    Ox[inp][i] += a * Hp.x;
                    Oy[inp][i] += a * Hp.y;
                }
            }
        __syncwarp();   // H reads complete before fp16 overlay
        u32* h2 = (u32*)(ws + bi*680);   // fp16x2, stride 36 u32
        #pragma unroll
        for (int inp = 0; inp < 2; inp++)
            #pragma unroll
            for (int n = 0; n < 5; n++){
                float sc = sm[SC1_OFF+n], sh = sm[SH1_OFF+n];
                float v0 = fmaxf(0.f, Ox[inp][n]*sc + sh);
                float v1 = fmaxf(0.f, Oy[inp][n]*sc + sh);
                h2[(inp*5 + n)*36 + lane] = pkh(v0, v1);
            }
        __syncwarp();
    }

    // ------- layer 2 MMA: 5 N-tiles (4 data + 1 score), K=64 in 4 k16-steps ------
    float4 d2[2][5];
    #pragma unroll
    for (int bi = 0; bi < 2; bi++)
        #pragma unroll
        for (int t = 0; t < 5; t++) d2[bi][t] = make_float4(0.f, 0.f, 0.f, 0.f);
    {
        const int hi_row2 = hi_ok ? (gid+8)*36 : 0;
        const u32* ha0lo = (const u32*)ws + gid*36 + tig;
        const u32* ha0hi = (const u32*)ws + hi_row2 + tig;
        const u32* ha1lo = ha0lo + 680;
        const u32* ha1hi = ha0hi + 680;
        const uint2* bf2 = (const uint2*)(sm + BF2_OFF);
        #pragma unroll
        for (int q = 0; q < 4; q++){
            u32 a00 = ha0lo[8*q], a01 = ha0hi[8*q];
            u32 a02 = ha0lo[8*q + 4], a03 = ha0hi[8*q + 4];
            u32 a10 = ha1lo[8*q], a11r = ha1hi[8*q];
            u32 a12r = ha1lo[8*q + 4], a13 = ha1hi[8*q + 4];
            #pragma unroll
            for (int t = 0; t < 5; t++){
                uint2 bb = bf2[(q*5 + t)*32 + lane];
                mma16(d2[0][t], a00, a01, a02, a03, bb.x, bb.y);
                mma16(d2[1][t], a10, a11r, a12r, a13, bb.x, bb.y);
            }
        }
    }
    __syncwarp();   // h2 reads done before hh overlay

    // ---- layer 2: scores direct from tile 4; spill hh rows (f32, stride 34) -----
    #pragma unroll
    for (int bi = 0; bi < 2; bi++){
        float2* sb2 = (float2*)(ws + 1400) + bi*10;
        if (tig == 0){
            sb2[gid] = make_float2(d2[bi][4].x, d2[bi][4].y);
            if (hi_ok) sb2[8 + gid] = make_float2(d2[bi][4].z, d2[bi][4].w);
        }
        float* hhb = ws + bi*680;   // f32, stride 34
        #pragma unroll
        for (int t = 0; t < 4; t++){
            int col = 8*t + 2*tig;
            *(float2*)(hhb + gid*34 + col) = make_float2(d2[bi][t].x, d2[bi][t].y);
            if (hi_ok)
                *(float2*)(hhb + (gid+8)*34 + col) = make_float2(d2[bi][t].z, d2[bi][t].w);
        }
    }
    __syncwarp();

    // ---------------- merged layer 2 softmax (20 lanes) -------------------------
    {
        int bb_ = lane / 10, r = lane - 10*bb_;
        int g = r / 5, j = r - 5*g;
        if (lane < 20){
            const float2* sb2 = (const float2*)(ws + 1400) + bb_*10;
            float* abuf = ws + 1440 + bb_*64;
            float t2j = sb2[(1-g)*5 + j].y;
            float ex[5], cs = 0.f;
            #pragma unroll
            for (int i = 0; i < 5; i++){
                float e = sb2[g*5 + i].x + t2j;
                e = (e > 0.f) ? e : ALPHA*e;
                ex[i] = __expf(e);
                cs += ex[i];
            }
            float rc = __fdividef(1.f, cs);
            #pragma unroll
            for (int i = 0; i < 5; i++) abuf[g*32 + i*5 + j] = ex[i]*rc;
        }
    }
    __syncwarp();

    // ---------------- apply2 + BN2 + ReLU ----------------
    float y2[2][2][5];
    #pragma unroll
    for (int bi = 0; bi < 2; bi++){
        const float* hhb = ws + bi*680;
        const float* abuf = ws + 1440 + bi*64;
        float hv[2][5];
        #pragma unroll
        for (int g = 0; g < 2; g++)
            #pragma unroll
            for (int j = 0; j < 5; j++)
                hv[g][j] = hhb[(g*5 + j)*34 + lane];
        #pragma unroll
        for (int g = 0; g < 2; g++)
            #pragma unroll
            for (int i = 0; i < 5; i++){
                float o2 = 0.f;
                #pragma unroll
                for (int j = 0; j < 5; j++)
                    o2 += abuf[g*32 + i*5 + j] * hv[g][j];
                y2[bi][g][i] = fmaxf(0.f, o2*sm[SC2_OFF+i] + sm[SH2_OFF+i]);
            }
    }

    // ---------------- final linear (shared Wl loads, both batches) --------------
    u64 f2a[5], f2b[5];
    #pragma unroll
    for (int n = 0; n < 5; n++){
        f2a[n] = pk(y2[0][0][n], y2[0][1][n]);
        f2b[n] = pk(y2[1][0][n], y2[1][1][n]);
    }
    const u64* wlp = (const u64*)(sm + WL2_OFF);
    float res0 = 0.f, res1 = 0.f;
    #pragma unroll
    for (int k = 0; k < 13; k++){
        u64 aa = 0ull, ab = 0ull;
        #pragma unroll
        for (int n = 0; n < 5; n++){
            u64 w = wlp[k*160 + n*32 + lane];
            aa = ffma2(f2a[n], w, aa);
            ab = ffma2(f2b[n], w, ab);
        }
        float r0 = wsum(hsum(aa));
        float r1 = wsum(hsum(ab));
        if (lane == k){ res0 = r0 + sm[BL_OFF+k]; res1 = r1 + sm[BL_OFF+k]; }
    }
    if (lane < 13){
        out[(size_t)b0i*13 + lane] = res0;
        if (has_b1) out[(size_t)b1i*13 + lane] = res1;
    }
}

extern "C" void kernel_launch(void* const* d_in, const int* in_sizes, int n_in,
                              void* d_out, int out_size)
{
    const float* x   = (const float*)d_in[0];
    const float* Wt1 = (const float*)d_in[1];
    const float* a11 = (const float*)d_in[2];
    const float* a21 = (const float*)d_in[3];
    const float* g1  = (const float*)d_in[4];
    const float* b1  = (const float*)d_in[5];
    const float* m1  = (const float*)d_in[6];
    const float* v1  = (const float*)d_in[7];
    const float* Wt2 = (const float*)d_in[8];
    const float* a12 = (const float*)d_in[9];
    const float* a22 = (const float*)d_in[10];
    const float* g2  = (const float*)d_in[11];
    const float* b2  = (const float*)d_in[12];
    const float* m2  = (const float*)d_in[13];
    const float* v2  = (const float*)d_in[14];
    const float* Wl  = (const float*)d_in[15];
    const float* bl  = (const float*)d_in[16];

    int B = in_sizes[0] / 1250;
    size_t smem_bytes = (size_t)SMEM_FLOATS * sizeof(float);
    cudaFuncSetAttribute(gat_fused_kernel,
                         cudaFuncAttributeMaxDynamicSharedMemorySize, (int)smem_bytes);

    int batches_per_block = WARPS * 2;
    dim3 grid((B + batches_per_block - 1) / batches_per_block);
    gat_fused_kernel<<<grid, THREADS, smem_bytes>>>(
        x, Wt1, a11, a21, g1, b1, m1, v1,
        Wt2, a12, a22, g2, b2, m2, v2, Wl, bl,
        (float*)d_out, B);
}